// round 17
// baseline (speedup 1.0000x reference)
#include <cuda_runtime.h>
#include <cstdint>

#define NB_EVENT 2000
#define NB_TYPE  10
#define PRED_LEN 1000
#define RBLK     20
#define NBLK     50           // PRED_LEN / RBLK
#define SEQB     224          // f32 exp(-w*dt)==0 beyond dt~208 for w>=0.5
#define CREW     704          // warps 0..21
#define MS       12           // matrix row stride (48B, 16B-aligned rows)

__device__ __forceinline__ float dot10v(const float* __restrict__ a,
                                        const float* __restrict__ b)
{
    const float4 x0 = *(const float4*)(a);
    const float4 y0 = *(const float4*)(b);
    const float4 x1 = *(const float4*)(a + 4);
    const float4 y1 = *(const float4*)(b + 4);
    const float2 x2 = *(const float2*)(a + 8);
    const float2 y2 = *(const float2*)(b + 8);
    const float p0 = x0.x*y0.x + x0.y*y0.y;
    const float p1 = x0.z*y0.z + x0.w*y0.w;
    const float p2 = x1.x*y1.x + x1.y*y1.y;
    const float p3 = x1.z*y1.z + x1.w*y1.w;
    const float p4 = x2.x*y2.x + x2.y*y2.y;
    return ((p0 + p1) + (p2 + p3)) + p4;
}

__global__ __launch_bounds__(1024, 1)
void hawkes_block(const int* __restrict__ seq_id,
                  const float* __restrict__ sequences,
                  const float* __restrict__ spontaneous,
                  const float* __restrict__ theta,
                  const float* __restrict__ w,
                  const float* __restrict__ alpha,
                  float* __restrict__ out)
{
    const int i    = blockIdx.x;          // 0..19: step-in-block column
    const int tid  = threadIdx.x;
    const int wid  = tid >> 5;
    const int lane = tid & 31;
    const int sid  = seq_id[0];
    const float* __restrict__ seq = sequences + (size_t)sid * NB_EVENT * NB_TYPE;

    __shared__ __align__(16) float sPw[21][120];      // M^0..M^20 (Pw[20] = P)
    __shared__ __align__(16) float sQ2[120], sQ3[120], sQ4[120], sQ8[120];
    __shared__ __align__(16) float sKi[120], sK20[120];
    __shared__ __align__(16) float sGi[120], sRi[120];
    __shared__ __align__(16) float sB [120];
    __shared__ __align__(16) float fv20[NBLK * MS];
    __shared__ __align__(16) float fve [NBLK * MS];   // ew ⊙ f
    __shared__ __align__(16) float sh  [NBLK * MS];   // h_t
    __shared__ __align__(16) float sh4 [46 * MS];     // h4_t for t = 0..45
    __shared__ __align__(16) float shh [2 * MS];
    __shared__ __align__(16) float sSt [NBLK * MS];
    __shared__ float erp [RBLK][NB_TYPE];
    __shared__ float sEW[10];
    __shared__ float sS0[16];

    #define BCAST10(v)                                                  \
        const float s0 = __shfl_sync(0xFFFFFFFFu, v, 0);                \
        const float s1 = __shfl_sync(0xFFFFFFFFu, v, 1);                \
        const float s2 = __shfl_sync(0xFFFFFFFFu, v, 2);                \
        const float s3 = __shfl_sync(0xFFFFFFFFu, v, 3);                \
        const float s4 = __shfl_sync(0xFFFFFFFFu, v, 4);                \
        const float s5 = __shfl_sync(0xFFFFFFFFu, v, 5);                \
        const float s6 = __shfl_sync(0xFFFFFFFFu, v, 6);                \
        const float s7 = __shfl_sync(0xFFFFFFFFu, v, 7);                \
        const float s8 = __shfl_sync(0xFFFFFFFFu, v, 8);                \
        const float s9 = __shfl_sync(0xFFFFFFFFu, v, 9)

    #define MATVEC(Sv, Mbase, addv)                                     \
    {                                                                   \
        BCAST10(Sv);                                                    \
        const float* __restrict__ _r = (Mbase) + k * MS;                \
        float _a = (addv);                                              \
        _a += _r[0]*s0; _a += _r[1]*s1; _a += _r[2]*s2; _a += _r[3]*s3; \
        _a += _r[4]*s4; _a += _r[5]*s5; _a += _r[6]*s6; _a += _r[7]*s7; \
        _a += _r[8]*s8; _a += _r[9]*s9;                                 \
        Sv = _a;                                                        \
    }

    if (wid >= 22) {
        // ================= copy slice + S0; never touches barrier 1 =================
        {
            const int ct = tid - CREW;                 // 0..319
            const float4* __restrict__ s4 = (const float4*)seq;
            float4* __restrict__ o4 = (float4*)out;
            if (ct < 250) o4[i * 250 + ct] = s4[i * 250 + ct];
        }
        const int k = wid - 22;                        // 0..9
        const float wk = w[sid * NB_TYPE + k];
        float d = expf(-wk * (float)(1 + lane));
        const float r = expf(-32.0f * wk);
        float acc = 0.0f;
        #pragma unroll
        for (int j = 0; j < SEQB / 32; j++) {
            const int e = (NB_EVENT - 1 - lane) - 32 * j;
            acc += seq[e * NB_TYPE + k] * d;
            d *= r;
        }
        #pragma unroll
        for (int off = 16; off > 0; off >>= 1)
            acc += __shfl_xor_sync(0xFFFFFFFFu, acc, off);
        if (lane == 0) sS0[k] = acc;
    } else {
        // ================= matrix crew: 704 threads =================
        #define CBAR asm volatile("bar.sync 1, %0;" :: "n"(CREW) : "memory")
        #define MMV(D, A, Bm, e)                                           \
        {                                                                  \
            const int kk = (e) / 10, jj = (e) - ((e) / 10) * 10;           \
            const float4 a0 = *(const float4*)((A) + kk * MS);             \
            const float4 a1 = *(const float4*)((A) + kk * MS + 4);         \
            const float2 a2 = *(const float2*)((A) + kk * MS + 8);         \
            float acc;                                                     \
            acc  = a0.x * (Bm)[0 * MS + jj];                               \
            acc += a0.y * (Bm)[1 * MS + jj];                               \
            acc += a0.z * (Bm)[2 * MS + jj];                               \
            acc += a0.w * (Bm)[3 * MS + jj];                               \
            acc += a1.x * (Bm)[4 * MS + jj];                               \
            acc += a1.y * (Bm)[5 * MS + jj];                               \
            acc += a1.z * (Bm)[6 * MS + jj];                               \
            acc += a1.w * (Bm)[7 * MS + jj];                               \
            acc += a2.x * (Bm)[8 * MS + jj];                               \
            acc += a2.y * (Bm)[9 * MS + jj];                               \
            (D)[kk * MS + jj] = acc;                                       \
        }

        // ---- r1 (pre): params, B, M, fv, fve, erp ----
        if (tid < 100) {
            const int k = tid / 10, j = tid - (tid / 10) * 10;
            const float alv = alpha[(size_t)sid * 100 + tid];
            const float wk  = w[sid * NB_TYPE + k];
            const float wj  = w[sid * NB_TYPE + j];
            const float ewk = expf(-wk);
            const float omj = 1.0f - expf(-wj);
            const float b   = alv * omj / wk;
            sB[k * MS + j] = b;
            sPw[1][k * MS + j] = ewk * ((k == j ? 1.0f : 0.0f) + b);
            sPw[0][k * MS + j] = (k == j) ? 1.0f : 0.0f;
            if (k == j) sEW[k] = ewk;
        } else if (tid < 600) {
            const int e = tid - 100;
            const int t = e / 10, m = e - (e / 10) * 10;
            const float th = theta[sid * NB_TYPE + m];
            const float sp = spontaneous[sid * NB_TYPE + m];
            const float ak = sp / th * (1.0f - expf(-th));
            const float v  = ak * expf(-th * (float)(NB_EVENT + RBLK * t));
            fv20[t * MS + m] = v;
            fve [t * MS + m] = v * expf(-w[sid * NB_TYPE + m]);
        } else {
            for (int e = tid - 600; e < 200; e += 104) {
                const int ii = e / 10, k = e - (e / 10) * 10;
                erp[ii][k] = expf(-theta[sid * NB_TYPE + k] * (float)ii);
            }
        }
        CBAR;
        // r2: M^2
        if (tid < 100) { MMV(sPw[2], sPw[1], sPw[1], tid); }
        CBAR;
        // r3: M^3, M^4
        if (tid < 200) { const int s = tid / 100, e = tid - s * 100; MMV(sPw[3 + s], sPw[2], sPw[1 + s], e); }
        CBAR;
        // r4: M^5..M^8
        if (tid < 400) { const int s = tid / 100, e = tid - s * 100; MMV(sPw[5 + s], sPw[4], sPw[1 + s], e); }
        CBAR;
        // r5: M^9..M^16
        for (int x = tid; x < 800; x += CREW) { const int s = x / 100, e = x - s * 100; MMV(sPw[9 + s], sPw[8], sPw[1 + s], e); }
        CBAR;
        // r6: M^17..M^20
        if (tid < 400) { const int s = tid / 100, e = tid - s * 100; MMV(sPw[17 + s], sPw[16], sPw[1 + s], e); }
        CBAR;
        // r7: K_i (100) + K_20 (100) + R_i (100) + Q2 = P^2 (100)
        if (tid < 400) {
            if (tid < 100) {
                const int k = tid / 10, m = tid - (tid / 10) * 10;
                float a = 0.0f;
                for (int j = 0; j < i; j++)
                    a += sPw[i - 1 - j][k * MS + m] * erp[j][m];
                sKi[k * MS + m] = a;
            } else if (tid < 200) {
                const int e = tid - 100;
                const int k = e / 10, m = e - (e / 10) * 10;
                float a = 0.0f;
                #pragma unroll
                for (int j = 0; j < 20; j++)
                    a += sPw[19 - j][k * MS + m] * erp[j][m];
                sK20[k * MS + m] = a;
            } else if (tid < 300) {
                const int e = tid - 200;
                MMV(sRi, sB, sPw[i], e);
            } else {
                const int e = tid - 300;
                MMV(sQ2, sPw[20], sPw[20], e);
            }
        }
        CBAR;
        // r8: G_i (100) + h_t (500) + Q3 (100) + Q4 (100)
        for (int x = tid; x < 800; x += CREW) {
            if (x < 100) {
                const int k = x / 10, m = x - (x / 10) * 10;
                float a = 0.0f;
                #pragma unroll
                for (int n = 0; n < 10; n++)
                    a += sB[k * MS + n] * sKi[n * MS + m];
                sGi[k * MS + m] = a * sEW[m];
            } else if (x < 600) {
                const int e = x - 100;
                const int t = e / 10, k = e - (e / 10) * 10;
                sh[t * MS + k] = dot10v(sK20 + k * MS, fve + t * MS);
            } else if (x < 700) {
                const int e = x - 600;
                MMV(sQ3, sQ2, sPw[20], e);
            } else {
                const int e = x - 700;
                MMV(sQ4, sQ2, sQ2, e);
            }
        }
        CBAR;
        // r9 (final): h4 for all t=0..45 (460) + hh (20) + Q8 = Q4*Q4 (100)
        if (tid < 580) {
            if (tid < 460) {
                const int t = tid / 10, k = tid - (tid / 10) * 10;
                float a = sh[(t + 3) * MS + k];
                a += dot10v(sPw[20] + k * MS, sh + (t + 2) * MS);
                a += dot10v(sQ2     + k * MS, sh + (t + 1) * MS);
                a += dot10v(sQ3     + k * MS, sh + t * MS);
                sh4[t * MS + k] = a;
            } else if (tid < 480) {
                const int e = tid - 460;
                const int t = e / 10, k = e - (e / 10) * 10;
                shh[t * MS + k] = sh[(t + 1) * MS + k]
                                + dot10v(sPw[20] + k * MS, sh + t * MS);
            } else {
                const int e = tid - 480;
                MMV(sQ8, sQ4, sQ4, e);
            }
        }
        #undef MMV
        #undef CBAR
    }
    __syncthreads();

    // ---- 8-way scan (warps 0..7) CONCURRENT with f-part (threads 512..761) ----
    // S_{t+8} = Q8*S_t + h8_t,  h8_t = Q4*h4_t + h4_{t+4}  (formed inline, off the S-chain)
    float af0 = 0.0f, af1 = 0.0f;
    int kk = 0, tt = 0;
    if (wid <= 7) {
        const bool act = (lane < NB_TYPE);
        const int  k   = act ? lane : 0;
        float Q8r[10];
        #pragma unroll
        for (int m = 0; m < 10; m++) Q8r[m] = sQ8[k * MS + m];

        float S = act ? sS0[k] : 0.0f;
        // seeds via log-chain
        if (wid == 0) {
        } else if (wid == 1) {
            MATVEC(S, sPw[20], sh[k]);                         // S1
        } else if (wid == 2) {
            MATVEC(S, sQ2, shh[k]);                            // S2
        } else if (wid == 3) {
            MATVEC(S, sPw[20], sh[k]);                         // S1
            MATVEC(S, sQ2, shh[MS + k]);                       // S3
        } else if (wid == 4) {
            MATVEC(S, sQ4, sh4[k]);                            // S4
        } else if (wid == 5) {
            MATVEC(S, sPw[20], sh[k]);                         // S1
            MATVEC(S, sQ4, sh4[MS + k]);                       // S5
        } else if (wid == 6) {
            MATVEC(S, sQ2, shh[k]);                            // S2
            MATVEC(S, sQ4, sh4[2 * MS + k]);                   // S6
        } else {
            MATVEC(S, sPw[20], sh[k]);                         // S1
            MATVEC(S, sQ2, shh[MS + k]);                       // S3
            MATVEC(S, sQ4, sh4[3 * MS + k]);                   // S7
        }
        if (act) sSt[wid * MS + k] = S;

        for (int t = wid; t <= 41; t += 8) {
            // h8 term: independent of S, schedules in the shuffle shadow
            const float h8 = dot10v(sQ4 + k * MS, sh4 + t * MS)
                           + sh4[(t + 4) * MS + k];
            BCAST10(S);
            const float p0 = Q8r[0]*s0, p1 = Q8r[1]*s1, p2 = Q8r[2]*s2, p3 = Q8r[3]*s3;
            const float p4 = Q8r[4]*s4, p5 = Q8r[5]*s5, p6 = Q8r[6]*s6, p7 = Q8r[7]*s7;
            const float p8 = Q8r[8]*s8, p9 = Q8r[9]*s9;
            const float q0 = p0+p1, q1 = p2+p3, q2 = p4+p5, q3 = p6+p7, q4 = p8+p9;
            const float r0 = q0+q1, r1 = q2+q3, r2 = q4+h8;
            S = (r0 + r1) + r2;
            if (act) sSt[(t + 8) * MS + k] = S;
        }
    } else if (tid >= 512 && tid < 762) {
        const int l = tid - 512;
        tt = l / 5;
        kk = 2 * (l - tt * 5);
        af0 = erp[i][kk]     * fv20[tt * MS + kk]
            + dot10v(sGi + kk * MS, fv20 + tt * MS);
        af1 = erp[i][kk + 1] * fv20[tt * MS + kk + 1]
            + dot10v(sGi + (kk + 1) * MS, fv20 + tt * MS);
    }
    __syncthreads();

    // ---- finish: add R_i * S_t, store ----
    if (tid >= 512 && tid < 762) {
        const float a0 = af0 + dot10v(sRi + kk * MS,       sSt + tt * MS);
        const float a1 = af1 + dot10v(sRi + (kk + 1) * MS, sSt + tt * MS);
        const int p = (tt * RBLK + i) * NB_TYPE + kk;
        *(float2*)(out + NB_EVENT * NB_TYPE + p) = make_float2(a0, a1);
    }
    #undef MATVEC
    #undef BCAST10
}

extern "C" void kernel_launch(void* const* d_in, const int* in_sizes, int n_in,
                              void* d_out, int out_size)
{
    const int*   seq_id      = (const int*)  d_in[0];
    const float* sequences   = (const float*)d_in[1];
    const float* spontaneous = (const float*)d_in[2];
    const float* theta       = (const float*)d_in[3];
    const float* w           = (const float*)d_in[4];
    const float* alpha       = (const float*)d_in[5];
    float* out = (float*)d_out;

    hawkes_block<<<RBLK, 1024>>>(seq_id, sequences, spontaneous, theta, w, alpha, out);
}